// round 14
// baseline (speedup 1.0000x reference)
#include <cuda_runtime.h>
#include <math.h>

// Problem constants
#define NT   1100            // 100 support + 1000 query
#define NTP  1152            // NT padded to multiple of 128 (GEMM tiles)
#define DM   640             // d_model
#define NSUP 100
#define SP   100             // 10*10 spatial
#define TK   10              // top-k
#define RB   256             // reduction blocks (fixed for determinism)
#define BMW  40              // bitmap words per row (ceil(1100/32)=35, padded)
#define NW   35              // bitmap words actually used

// ---------------- scratch (device globals; no allocation allowed) ----------
__device__ float    g_x  [NTP * DM];             // spatial means (padded rows = 0)
__device__ float    g_q  [NTP * DM];             // emb_q
__device__ float    g_v  [NTP * DM];             // emb_v
__device__ float    g_qp0[NTP * DM];             // K-split partials
__device__ float    g_qp1[NTP * DM];
__device__ float    g_vp0[NTP * DM];
__device__ float    g_vp1[NTP * DM];
__device__ float    g_gp0[(size_t)NTP * NTP];    // gram K-split partials
__device__ float    g_gp1[(size_t)NTP * NTP];
__device__ float    g_sq [NT];                   // ||emb_q_i||^2
__device__ float    g_w  [(size_t)NT * NT];      // distances, then exp-kernel
__device__ int      g_tk [NT * TK];              // topk indices per row
__device__ unsigned g_bm [NT * BMW];             // symmetric adjacency bitmap
__device__ float    g_dsi[NT];                   // D^{-1/2}
__device__ double   g_ps [RB];                   // partial sums
__device__ double   g_pq [RB];                   // partial sums of squares
__device__ float    g_invstd;

// ---------------- 1) spatial mean: x[n,c] = mean_s emb[n,c,s] --------------
__global__ void mean_kernel(const float* __restrict__ sup,
                            const float* __restrict__ qry) {
    int gw   = (blockIdx.x * blockDim.x + threadIdx.x) >> 5;
    int lane = threadIdx.x & 31;
    if (gw >= NT * DM) return;
    int n = gw / DM, c = gw - n * DM;
    const float* p = (n < NSUP)
        ? (sup + (size_t)n * DM * SP + (size_t)c * SP)
        : (qry + (size_t)(n - NSUP) * DM * SP + (size_t)c * SP);
    float s = 0.f;
    if (lane < 25) {
        float4 v = ((const float4*)p)[lane];
        s = (v.x + v.y) + (v.z + v.w);
    }
#pragma unroll
    for (int o = 16; o > 0; o >>= 1) s += __shfl_down_sync(0xffffffffu, s, o);
    if (lane == 0) g_x[gw] = s * (1.0f / SP);
}

// ---------------- K-split fp32 GEMM: 128x64 tile, 8x4 micro, dbl-buffered --
// Partial C = A[:,koff:koff+K/2] @ B[:,koff:koff+K/2]^T  (both K-major rows).
// All loads AND stores unguarded: A rows >= gridDim.y*128, B rows >=
// gridDim.x*64, C is a full padded partial buffer with pitch ldc.
// gridDim.z == 4: z = (wsel | ksel<<1), B = wsel?B1:B0, C = Cz.
// gridDim.z == 2: z = ksel, B = B0, C = (z?C1:C0).
__global__ void __launch_bounds__(256)
gemm_ksplit(const float* __restrict__ A,
            const float* __restrict__ B0, const float* __restrict__ B1,
            float* __restrict__ C0, float* __restrict__ C1,
            float* __restrict__ C2, float* __restrict__ C3,
            int Kfull, int ldc) {
    int z = blockIdx.z;
    int wsel, ksel;
    if (gridDim.z == 4) { wsel = z & 1; ksel = z >> 1; }
    else                { wsel = 0;     ksel = z;      }
    const float* __restrict__ B = wsel ? B1 : B0;
    float* __restrict__ C = (z == 0) ? C0 : (z == 1) ? C1 : (z == 2) ? C2 : C3;
    int Khalf = Kfull >> 1;
    int koff  = ksel * Khalf;

    __shared__ float As[2][8][132];   // k-major, conflict-free pitch
    __shared__ float Bs[2][8][68];

    int row0 = blockIdx.y * 128, col0 = blockIdx.x * 64;
    int tid = threadIdx.x;            // 256 threads
    int tx = tid & 15, ty = tid >> 4; // micro 8(rows) x 4(cols)
    int arow = tid >> 1,          ah = tid & 1;   // A: 128 rows x 2 half-k
    int brow = (tid & 127) >> 1,  bh = tid & 1;   // B: 64 rows x 2 half-k

    const float4* Ap = (const float4*)(A + (size_t)(row0 + arow) * Kfull + koff + ah * 4);
    const float4* Bp = (const float4*)(B + (size_t)(col0 + brow) * Kfull + koff + bh * 4);

    float acc[8][4] = {};
    int nk = Khalf >> 3;
    // Kfull/8 float4 per row advance per 8-k tile => stride in float4 = Kfull/4? No:
    // Ap indexes float4 within the row; +8 floats per tile = +2 float4.

    float4 av = Ap[0];
    float4 bv = make_float4(0.f, 0.f, 0.f, 0.f);
    if (tid < 128) bv = Bp[0];

    int buf = 0;
    As[buf][ah * 4 + 0][arow] = av.x;
    As[buf][ah * 4 + 1][arow] = av.y;
    As[buf][ah * 4 + 2][arow] = av.z;
    As[buf][ah * 4 + 3][arow] = av.w;
    if (tid < 128) {
        Bs[buf][bh * 4 + 0][brow] = bv.x;
        Bs[buf][bh * 4 + 1][brow] = bv.y;
        Bs[buf][bh * 4 + 2][brow] = bv.z;
        Bs[buf][bh * 4 + 3][brow] = bv.w;
    }
    __syncthreads();

    for (int kt = 1; kt < nk; kt++) {
        av = Ap[kt * 2];
        if (tid < 128) bv = Bp[kt * 2];

        const float (*as)[132] = As[buf];
        const float (*bs)[68]  = Bs[buf];
#pragma unroll
        for (int k = 0; k < 8; k++) {
            float4 a0 = *(const float4*)&as[k][ty * 8];
            float4 a1 = *(const float4*)&as[k][ty * 8 + 4];
            float4 b4 = *(const float4*)&bs[k][tx * 4];
            float a[8] = {a0.x, a0.y, a0.z, a0.w, a1.x, a1.y, a1.z, a1.w};
            float b[4] = {b4.x, b4.y, b4.z, b4.w};
#pragma unroll
            for (int i = 0; i < 8; i++)
#pragma unroll
                for (int j = 0; j < 4; j++) acc[i][j] += a[i] * b[j];
        }
        int nb = buf ^ 1;
        As[nb][ah * 4 + 0][arow] = av.x;
        As[nb][ah * 4 + 1][arow] = av.y;
        As[nb][ah * 4 + 2][arow] = av.z;
        As[nb][ah * 4 + 3][arow] = av.w;
        if (tid < 128) {
            Bs[nb][bh * 4 + 0][brow] = bv.x;
            Bs[nb][bh * 4 + 1][brow] = bv.y;
            Bs[nb][bh * 4 + 2][brow] = bv.z;
            Bs[nb][bh * 4 + 3][brow] = bv.w;
        }
        __syncthreads();
        buf = nb;
    }
    {   // last tile
        const float (*as)[132] = As[buf];
        const float (*bs)[68]  = Bs[buf];
#pragma unroll
        for (int k = 0; k < 8; k++) {
            float4 a0 = *(const float4*)&as[k][ty * 8];
            float4 a1 = *(const float4*)&as[k][ty * 8 + 4];
            float4 b4 = *(const float4*)&bs[k][tx * 4];
            float a[8] = {a0.x, a0.y, a0.z, a0.w, a1.x, a1.y, a1.z, a1.w};
            float b[4] = {b4.x, b4.y, b4.z, b4.w};
#pragma unroll
            for (int i = 0; i < 8; i++)
#pragma unroll
                for (int j = 0; j < 4; j++) acc[i][j] += a[i] * b[j];
        }
    }

    // unguarded vectorized store of the partial tile
#pragma unroll
    for (int i = 0; i < 8; i++) {
        int r = row0 + ty * 8 + i;
        float4 o = make_float4(acc[i][0], acc[i][1], acc[i][2], acc[i][3]);
        *(float4*)(C + (size_t)r * ldc + col0 + tx * 4) = o;
    }
}

// ---------------- combine qv partials + fused ||q||^2 ----------------------
// one block per padded row; 160 threads = DM/4 float4 lanes
__global__ void __launch_bounds__(160) combine_qv_kernel() {
    int r = blockIdx.x;                 // 0..NTP-1
    int t = threadIdx.x;                // 0..159
    size_t base = (size_t)r * DM;
    float4 q0 = ((const float4*)(g_qp0 + base))[t];
    float4 q1 = ((const float4*)(g_qp1 + base))[t];
    float4 q  = make_float4(q0.x + q1.x, q0.y + q1.y, q0.z + q1.z, q0.w + q1.w);
    ((float4*)(g_q + base))[t] = q;
    float4 v0 = ((const float4*)(g_vp0 + base))[t];
    float4 v1 = ((const float4*)(g_vp1 + base))[t];
    ((float4*)(g_v + base))[t] =
        make_float4(v0.x + v1.x, v0.y + v1.y, v0.z + v1.z, v0.w + v1.w);

    // block-reduce sum of q^2 (5 warps)
    float s = q.x * q.x + q.y * q.y + q.z * q.z + q.w * q.w;
#pragma unroll
    for (int o = 16; o > 0; o >>= 1) s += __shfl_down_sync(0xffffffffu, s, o);
    __shared__ float ws[5];
    if ((t & 31) == 0) ws[t >> 5] = s;
    __syncthreads();
    if (t == 0 && r < NT)
        g_sq[r] = (ws[0] + ws[1]) + (ws[2] + ws[3]) + ws[4];
}

// ---------------- combine gram partials -> distances + fused sum/sumsq -----
// row-strided over blocks (no integer division); writes w (NT x NT)
__global__ void __launch_bounds__(256) combine_gram_kernel() {
    int tid = threadIdx.x;
    double s = 0.0, q = 0.0;
    for (int i = blockIdx.x; i < NT; i += gridDim.x) {
        float sqi = g_sq[i];
        const float* p0 = g_gp0 + (size_t)i * NTP;
        const float* p1 = g_gp1 + (size_t)i * NTP;
        float* wrow = g_w + (size_t)i * NT;
        for (int j = tid; j < NT; j += 256) {
            float p = p0[j] + p1[j];
            float d = (i == j) ? 0.f : fmaxf(sqi + g_sq[j] - 2.0f * p, 0.f);
            wrow[j] = d;
            double dv = (double)d;
            s += dv; q += dv * dv;
        }
    }
    __shared__ double ss[256], qq[256];
    ss[tid] = s; qq[tid] = q; __syncthreads();
    for (int st = 128; st > 0; st >>= 1) {
        if (tid < st) { ss[tid] += ss[tid + st]; qq[tid] += qq[tid + st]; }
        __syncthreads();
    }
    if (tid == 0) { g_ps[blockIdx.x] = ss[0]; g_pq[blockIdx.x] = qq[0]; }
}

__global__ void reduce_final_kernel() {
    __shared__ double ss[RB], qq[RB];
    ss[threadIdx.x] = g_ps[threadIdx.x];
    qq[threadIdx.x] = g_pq[threadIdx.x];
    __syncthreads();
    for (int st = RB / 2; st > 0; st >>= 1) {
        if (threadIdx.x < st) {
            ss[threadIdx.x] += ss[threadIdx.x + st];
            qq[threadIdx.x] += qq[threadIdx.x + st];
        }
        __syncthreads();
    }
    if (threadIdx.x == 0) {
        // diag entries are exactly 0 => sums over all == sums over off-diag
        double cnt = (double)NT * NT - NT;
        double sum = ss[0], sumsq = qq[0];
        double var = (sumsq - sum * sum / cnt) / (cnt - 1.0);   // unbiased
        g_invstd = (float)(1.0 / sqrt(var));
    }
}

// ---------------- fused transform + per-row top-10 (warp per row) ----------
// w := exp(-0.5 * w * invstd)  (diag 0 -> 1), then iterative argmax,
// ties broken to lowest index (matches jax.lax.top_k).
__global__ void topk_kernel() {
    int gw   = (blockIdx.x * blockDim.x + threadIdx.x) >> 5;
    int lane = threadIdx.x & 31;
    if (gw >= NT) return;
    float is = g_invstd;
    float* row = g_w + (size_t)gw * NT;
    float vals[NW];
#pragma unroll
    for (int s = 0; s < NW; s++) {
        int j = lane + 32 * s;
        float e = -2.f;
        if (j < NT) { e = __expf(-0.5f * row[j] * is); row[j] = e; }
        vals[s] = e;
    }
    for (int t = 0; t < TK; t++) {
        float best = -3.f; int bslot = 0;
#pragma unroll
        for (int s = 0; s < NW; s++) {        // strict > keeps lowest j in-lane
            if (vals[s] > best) { best = vals[s]; bslot = s; }
        }
        int bj = lane + 32 * bslot;
#pragma unroll
        for (int o = 16; o > 0; o >>= 1) {
            float ov = __shfl_down_sync(0xffffffffu, best, o);
            int   oj = __shfl_down_sync(0xffffffffu, bj,   o);
            if (ov > best || (ov == best && oj < bj)) { best = ov; bj = oj; }
        }
        bj = __shfl_sync(0xffffffffu, bj, 0);
        if (lane == 0) g_tk[gw * TK + t] = bj;
        if ((bj & 31) == lane) vals[bj >> 5] = -2.f;   // exclude (values in (0,1])
    }
}

// ---------------- symmetric adjacency bitmap from top-k lists --------------
__global__ void edge_kernel() {
    int idx = blockIdx.x * blockDim.x + threadIdx.x;
    if (idx >= NT * TK) return;
    int i = idx / TK;
    int j = g_tk[idx];
    atomicOr(&g_bm[i * BMW + (j >> 5)], 1u << (j & 31));
    atomicOr(&g_bm[j * BMW + (i >> 5)], 1u << (i & 31));
}

// ---------------- degree (row sums over mask; w is bitwise symmetric) ------
__global__ void deg_kernel() {
    int gw   = (blockIdx.x * blockDim.x + threadIdx.x) >> 5;
    int lane = threadIdx.x & 31;
    if (gw >= NT) return;
    float s = 0.f;
    for (int wi = lane; wi < NW; wi += 32) {
        unsigned m = g_bm[gw * BMW + wi];
        while (m) {
            int b = __ffs(m) - 1; m &= m - 1;
            s += g_w[(size_t)gw * NT + wi * 32 + b];
        }
    }
#pragma unroll
    for (int o = 16; o > 0; o >>= 1) s += __shfl_down_sync(0xffffffffu, s, o);
    if (lane == 0) g_dsi[gw] = sqrtf(1.0f / (s + 2.2204460492503131e-16f));
}

// ---------------- sparse out[i,:] = dsi_i * sum_j w_ij*dsi_j * v[j,:] ------
__global__ void spout_kernel(float* __restrict__ out) {
    int i = blockIdx.x;
    __shared__ int   nbr[1120];
    __shared__ float coef[1120];
    __shared__ int   s_cnt;
    int tid = threadIdx.x;
    if (tid == 0) {
        int off = 0;
        for (int wi = 0; wi < NW; wi++) {            // cover all 1100 columns
            unsigned m = g_bm[i * BMW + wi];
            while (m) {
                int b = __ffs(m) - 1; m &= m - 1;
                nbr[off++] = wi * 32 + b;
            }
        }
        s_cnt = off;
    }
    __syncthreads();
    int cnt = s_cnt;
    for (int t = tid; t < cnt; t += blockDim.x) {
        int j = nbr[t];
        coef[t] = g_w[(size_t)i * NT + j] * g_dsi[j];
    }
    __syncthreads();
    float di = g_dsi[i];
    for (int c = tid; c < DM; c += blockDim.x) {
        float acc = 0.f;
        for (int t = 0; t < cnt; t++)
            acc += coef[t] * g_v[(size_t)nbr[t] * DM + c];
        out[(size_t)i * DM + c] = di * acc;
    }
}

// ---------------- host launcher --------------------------------------------
extern "C" void kernel_launch(void* const* d_in, const int* in_sizes, int n_in,
                              void* d_out, int out_size) {
    const float* sup = (const float*)d_in[0];   // [100,640,10,10]
    const float* qry = (const float*)d_in[2];   // [1000,640,10,10]
    const float* Wq  = (const float*)d_in[4];   // [640,640]
    const float* Wv  = (const float*)d_in[5];   // [640,640]
    float* out = (float*)d_out;                 // [1100,640]

    float *px, *pq, *pqp0, *pqp1, *pvp0, *pvp1, *pgp0, *pgp1;
    void* pbm;
    cudaGetSymbolAddress((void**)&px,  g_x);
    cudaGetSymbolAddress((void**)&pq,  g_q);
    cudaGetSymbolAddress((void**)&pqp0, g_qp0);
    cudaGetSymbolAddress((void**)&pqp1, g_qp1);
    cudaGetSymbolAddress((void**)&pvp0, g_vp0);
    cudaGetSymbolAddress((void**)&pvp1, g_vp1);
    cudaGetSymbolAddress((void**)&pgp0, g_gp0);
    cudaGetSymbolAddress((void**)&pgp1, g_gp1);
    cudaGetSymbolAddress(&pbm, g_bm);

    // zero the padding rows of g_x (pad rows propagate as zeros through GEMMs)
    cudaMemsetAsync(px + (size_t)NT * DM, 0, (size_t)(NTP - NT) * DM * sizeof(float));

    // 1) spatial mean
    mean_kernel<<<(NT * DM * 32 + 255) / 256, 256>>>(sup, qry);

    // 2) emb_q / emb_v = x @ W^T, K-split=2 fused over both weights (z=4)
    {
        dim3 grid(DM / 64, NTP / 128, 4);
        gemm_ksplit<<<grid, 256>>>(px, Wq, Wv, pqp0, pvp0, pqp1, pvp1, DM, DM);
    }
    // combine partials + fused sq norms
    combine_qv_kernel<<<NTP, 160>>>();

    // 3) Gram = emb_q @ emb_q^T, K-split=2
    {
        dim3 grid(NTP / 64, NTP / 128, 2);
        gemm_ksplit<<<grid, 256>>>(pq, pq, pq, pgp0, pgp1, pgp0, pgp1, DM, NTP);
    }
    // combine + distance epilogue + fused variance partials
    combine_gram_kernel<<<RB, 256>>>();
    reduce_final_kernel<<<1, RB>>>();

    // 4) fused exp transform + top-k
    int wr_blocks = (NT * 32 + 255) / 256;
    topk_kernel<<<wr_blocks, 256>>>();

    // 5) symmetric mask bitmap + degrees
    cudaMemsetAsync(pbm, 0, sizeof(unsigned) * NT * BMW);
    edge_kernel<<<(NT * TK + 255) / 256, 256>>>();
    deg_kernel<<<wr_blocks, 256>>>();

    // 6) sparse S @ emb_v with Laplacian scaling folded in
    spout_kernel<<<NT, 256>>>(out);
}

// round 15
// speedup vs baseline: 1.0547x; 1.0547x over previous
#include <cuda_runtime.h>
#include <math.h>

// Problem constants
#define NT   1100            // 100 support + 1000 query
#define NTP  1152            // NT padded to multiple of 128 (GEMM tiles)
#define DM   640             // d_model
#define NSUP 100
#define SP   100             // 10*10 spatial
#define TK   10              // top-k
#define RB   256             // reduction blocks (fixed for determinism)
#define BMW  40              // bitmap words per row (ceil(1100/32)=35, padded)
#define NW   35              // bitmap words actually used

// ---------------- scratch (device globals; no allocation allowed) ----------
__device__ float    g_x  [NTP * DM];             // spatial means (padded rows = 0)
__device__ float    g_q  [NTP * DM];             // emb_q
__device__ float    g_v  [NTP * DM];             // emb_v
__device__ float    g_qp0[NTP * DM];             // K-split partials
__device__ float    g_qp1[NTP * DM];
__device__ float    g_vp0[NTP * DM];
__device__ float    g_vp1[NTP * DM];
__device__ float    g_gp0[(size_t)NTP * NTP];    // gram K-split partials
__device__ float    g_gp1[(size_t)NTP * NTP];
__device__ float    g_sq [NT];                   // ||emb_q_i||^2
__device__ float    g_w  [(size_t)NT * NT];      // distances, then exp-kernel
__device__ int      g_tk [NT * TK];              // topk indices per row
__device__ unsigned g_bm [NT * BMW];             // symmetric adjacency bitmap
__device__ float    g_dsi[NT];                   // D^{-1/2}
__device__ double   g_ps [RB];                   // partial sums
__device__ double   g_pq [RB];                   // partial sums of squares
__device__ float    g_invstd;

// packed f32x2 FMA (Blackwell; ptxas never emits FFMA2 from C++ — PTX only)
#define FMA2(acc, a, b) \
    asm("fma.rn.f32x2 %0, %1, %2, %0;" : "+l"(acc) : "l"(a), "l"(b))

// ---------------- 1) spatial mean: x[n,c] = mean_s emb[n,c,s] --------------
__global__ void mean_kernel(const float* __restrict__ sup,
                            const float* __restrict__ qry) {
    int gw   = (blockIdx.x * blockDim.x + threadIdx.x) >> 5;
    int lane = threadIdx.x & 31;
    if (gw >= NT * DM) return;
    int n = gw / DM, c = gw - n * DM;
    const float* p = (n < NSUP)
        ? (sup + (size_t)n * DM * SP + (size_t)c * SP)
        : (qry + (size_t)(n - NSUP) * DM * SP + (size_t)c * SP);
    float s = 0.f;
    if (lane < 25) {
        float4 v = ((const float4*)p)[lane];
        s = (v.x + v.y) + (v.z + v.w);
    }
#pragma unroll
    for (int o = 16; o > 0; o >>= 1) s += __shfl_down_sync(0xffffffffu, s, o);
    if (lane == 0) g_x[gw] = s * (1.0f / SP);
}

// ---------------- K-split fp32 GEMM (FFMA2 core) ---------------------------
// 128x64 tile, 8x4 micro, double-buffered; inner product done with packed
// fma.rn.f32x2: accumulators hold row pairs (2p, 2p+1) in (lo, hi).
// Partial C = A[:,koff:+K/2] @ B[:,koff:+K/2]^T; loads/stores unguarded
// (padded buffers). gridDim.z==4: z=(wsel|ksel<<1); gridDim.z==2: z=ksel.
__global__ void __launch_bounds__(256, 3)
gemm_ksplit(const float* __restrict__ A,
            const float* __restrict__ B0, const float* __restrict__ B1,
            float* __restrict__ C0, float* __restrict__ C1,
            float* __restrict__ C2, float* __restrict__ C3,
            int Kfull, int ldc) {
    int z = blockIdx.z;
    int wsel, ksel;
    if (gridDim.z == 4) { wsel = z & 1; ksel = z >> 1; }
    else                { wsel = 0;     ksel = z;      }
    const float* __restrict__ B = wsel ? B1 : B0;
    float* __restrict__ C = (z == 0) ? C0 : (z == 1) ? C1 : (z == 2) ? C2 : C3;
    int Khalf = Kfull >> 1;
    int koff  = ksel * Khalf;

    __shared__ __align__(16) float As[2][8][132];   // k-major, pitch 132 (528B, 16B-mult)
    __shared__ __align__(16) float Bs[2][8][68];    // pitch 68 (272B, 16B-mult)

    int row0 = blockIdx.y * 128, col0 = blockIdx.x * 64;
    int tid = threadIdx.x;            // 256 threads
    int tx = tid & 15, ty = tid >> 4; // micro 8(rows) x 4(cols)
    int arow = tid >> 1,          ah = tid & 1;   // A: 128 rows x 2 half-k
    int brow = (tid & 127) >> 1,  bh = tid & 1;   // B: 64 rows x 2 half-k

    const float4* Ap = (const float4*)(A + (size_t)(row0 + arow) * Kfull + koff + ah * 4);
    const float4* Bp = (const float4*)(B + (size_t)(col0 + brow) * Kfull + koff + bh * 4);

    // shared-space base addresses for inline-PTX loads
    unsigned sA = (unsigned)__cvta_generic_to_shared(&As[0][0][0]);
    unsigned sB = (unsigned)__cvta_generic_to_shared(&Bs[0][0][0]);
    const unsigned ASZ = 8 * 132 * 4, BSZ = 8 * 68 * 4;

    unsigned long long acc[4][4];     // [row-pair][col], packed f32x2
#pragma unroll
    for (int p = 0; p < 4; p++)
#pragma unroll
        for (int j = 0; j < 4; j++) acc[p][j] = 0ull;

    int nk = Khalf >> 3;

    float4 av = Ap[0];
    float4 bv = make_float4(0.f, 0.f, 0.f, 0.f);
    if (tid < 128) bv = Bp[0];

    int buf = 0;
    As[buf][ah * 4 + 0][arow] = av.x;
    As[buf][ah * 4 + 1][arow] = av.y;
    As[buf][ah * 4 + 2][arow] = av.z;
    As[buf][ah * 4 + 3][arow] = av.w;
    if (tid < 128) {
        Bs[buf][bh * 4 + 0][brow] = bv.x;
        Bs[buf][bh * 4 + 1][brow] = bv.y;
        Bs[buf][bh * 4 + 2][brow] = bv.z;
        Bs[buf][bh * 4 + 3][brow] = bv.w;
    }
    __syncthreads();

#define GEMM_INNER8(bufA, bufB)                                                  \
    _Pragma("unroll")                                                            \
    for (int k = 0; k < 8; k++) {                                                \
        unsigned aaddr = (bufA) + k * 528 + ty * 32;                             \
        unsigned baddr = (bufB) + k * 272 + tx * 16;                             \
        unsigned long long a0, a1, a2, a3, bd0, bd1, bd2, bd3;                   \
        float b0, b1, b2, b3;                                                    \
        asm volatile("ld.shared.v2.b64 {%0,%1}, [%2];"                           \
                     : "=l"(a0), "=l"(a1) : "r"(aaddr));                         \
        asm volatile("ld.shared.v2.b64 {%0,%1}, [%2];"                           \
                     : "=l"(a2), "=l"(a3) : "r"(aaddr + 16));                    \
        asm volatile("ld.shared.v4.f32 {%0,%1,%2,%3}, [%4];"                     \
                     : "=f"(b0), "=f"(b1), "=f"(b2), "=f"(b3) : "r"(baddr));     \
        asm("mov.b64 %0, {%1,%1};" : "=l"(bd0) : "f"(b0));                       \
        asm("mov.b64 %0, {%1,%1};" : "=l"(bd1) : "f"(b1));                       \
        asm("mov.b64 %0, {%1,%1};" : "=l"(bd2) : "f"(b2));                       \
        asm("mov.b64 %0, {%1,%1};" : "=l"(bd3) : "f"(b3));                       \
        FMA2(acc[0][0], a0, bd0); FMA2(acc[0][1], a0, bd1);                      \
        FMA2(acc[0][2], a0, bd2); FMA2(acc[0][3], a0, bd3);                      \
        FMA2(acc[1][0], a1, bd0); FMA2(acc[1][1], a1, bd1);                      \
        FMA2(acc[1][2], a1, bd2); FMA2(acc[1][3], a1, bd3);                      \
        FMA2(acc[2][0], a2, bd0); FMA2(acc[2][1], a2, bd1);                      \
        FMA2(acc[2][2], a2, bd2); FMA2(acc[2][3], a2, bd3);                      \
        FMA2(acc[3][0], a3, bd0); FMA2(acc[3][1], a3, bd1);                      \
        FMA2(acc[3][2], a3, bd2); FMA2(acc[3][3], a3, bd3);                      \
    }

    for (int kt = 1; kt < nk; kt++) {
        av = Ap[kt * 2];
        if (tid < 128) bv = Bp[kt * 2];

        unsigned bufA = sA + buf * ASZ;
        unsigned bufB = sB + buf * BSZ;
        GEMM_INNER8(bufA, bufB);

        int nb = buf ^ 1;
        As[nb][ah * 4 + 0][arow] = av.x;
        As[nb][ah * 4 + 1][arow] = av.y;
        As[nb][ah * 4 + 2][arow] = av.z;
        As[nb][ah * 4 + 3][arow] = av.w;
        if (tid < 128) {
            Bs[nb][bh * 4 + 0][brow] = bv.x;
            Bs[nb][bh * 4 + 1][brow] = bv.y;
            Bs[nb][bh * 4 + 2][brow] = bv.z;
            Bs[nb][bh * 4 + 3][brow] = bv.w;
        }
        __syncthreads();
        buf = nb;
    }
    {   // last tile
        unsigned bufA = sA + buf * ASZ;
        unsigned bufB = sB + buf * BSZ;
        GEMM_INNER8(bufA, bufB);
    }
#undef GEMM_INNER8

    // unpack row pairs and store (unguarded, padded partial buffers)
#pragma unroll
    for (int p = 0; p < 4; p++) {
        float lo[4], hi[4];
#pragma unroll
        for (int j = 0; j < 4; j++)
            asm("mov.b64 {%0,%1}, %2;" : "=f"(lo[j]), "=f"(hi[j]) : "l"(acc[p][j]));
        int r = row0 + ty * 8 + p * 2;
        *(float4*)(C + (size_t)r * ldc + col0 + tx * 4) =
            make_float4(lo[0], lo[1], lo[2], lo[3]);
        *(float4*)(C + (size_t)(r + 1) * ldc + col0 + tx * 4) =
            make_float4(hi[0], hi[1], hi[2], hi[3]);
    }
}

// ---------------- combine qv partials + fused ||q||^2 ----------------------
__global__ void __launch_bounds__(160) combine_qv_kernel() {
    int r = blockIdx.x;                 // 0..NTP-1
    int t = threadIdx.x;                // 0..159
    size_t base = (size_t)r * DM;
    float4 q0 = ((const float4*)(g_qp0 + base))[t];
    float4 q1 = ((const float4*)(g_qp1 + base))[t];
    float4 q  = make_float4(q0.x + q1.x, q0.y + q1.y, q0.z + q1.z, q0.w + q1.w);
    ((float4*)(g_q + base))[t] = q;
    float4 v0 = ((const float4*)(g_vp0 + base))[t];
    float4 v1 = ((const float4*)(g_vp1 + base))[t];
    ((float4*)(g_v + base))[t] =
        make_float4(v0.x + v1.x, v0.y + v1.y, v0.z + v1.z, v0.w + v1.w);

    float s = q.x * q.x + q.y * q.y + q.z * q.z + q.w * q.w;
#pragma unroll
    for (int o = 16; o > 0; o >>= 1) s += __shfl_down_sync(0xffffffffu, s, o);
    __shared__ float ws[5];
    if ((t & 31) == 0) ws[t >> 5] = s;
    __syncthreads();
    if (t == 0 && r < NT)
        g_sq[r] = (ws[0] + ws[1]) + (ws[2] + ws[3]) + ws[4];
}

// ---------------- combine gram partials -> distances + fused sum/sumsq -----
__global__ void __launch_bounds__(256) combine_gram_kernel() {
    int tid = threadIdx.x;
    double s = 0.0, q = 0.0;
    for (int i = blockIdx.x; i < NT; i += gridDim.x) {
        float sqi = g_sq[i];
        const float* p0 = g_gp0 + (size_t)i * NTP;
        const float* p1 = g_gp1 + (size_t)i * NTP;
        float* wrow = g_w + (size_t)i * NT;
        for (int j = tid; j < NT; j += 256) {
            float p = p0[j] + p1[j];
            float d = (i == j) ? 0.f : fmaxf(sqi + g_sq[j] - 2.0f * p, 0.f);
            wrow[j] = d;
            double dv = (double)d;
            s += dv; q += dv * dv;
        }
    }
    __shared__ double ss[256], qq[256];
    ss[tid] = s; qq[tid] = q; __syncthreads();
    for (int st = 128; st > 0; st >>= 1) {
        if (tid < st) { ss[tid] += ss[tid + st]; qq[tid] += qq[tid + st]; }
        __syncthreads();
    }
    if (tid == 0) { g_ps[blockIdx.x] = ss[0]; g_pq[blockIdx.x] = qq[0]; }
}

__global__ void reduce_final_kernel() {
    __shared__ double ss[RB], qq[RB];
    ss[threadIdx.x] = g_ps[threadIdx.x];
    qq[threadIdx.x] = g_pq[threadIdx.x];
    __syncthreads();
    for (int st = RB / 2; st > 0; st >>= 1) {
        if (threadIdx.x < st) {
            ss[threadIdx.x] += ss[threadIdx.x + st];
            qq[threadIdx.x] += qq[threadIdx.x + st];
        }
        __syncthreads();
    }
    if (threadIdx.x == 0) {
        double cnt = (double)NT * NT - NT;
        double sum = ss[0], sumsq = qq[0];
        double var = (sumsq - sum * sum / cnt) / (cnt - 1.0);   // unbiased
        g_invstd = (float)(1.0 / sqrt(var));
    }
}

// ---------------- fused transform + per-row top-10 (warp per row) ----------
__global__ void topk_kernel() {
    int gw   = (blockIdx.x * blockDim.x + threadIdx.x) >> 5;
    int lane = threadIdx.x & 31;
    if (gw >= NT) return;
    float is = g_invstd;
    float* row = g_w + (size_t)gw * NT;
    float vals[NW];
#pragma unroll
    for (int s = 0; s < NW; s++) {
        int j = lane + 32 * s;
        float e = -2.f;
        if (j < NT) { e = __expf(-0.5f * row[j] * is); row[j] = e; }
        vals[s] = e;
    }
    for (int t = 0; t < TK; t++) {
        float best = -3.f; int bslot = 0;
#pragma unroll
        for (int s = 0; s < NW; s++) {
            if (vals[s] > best) { best = vals[s]; bslot = s; }
        }
        int bj = lane + 32 * bslot;
#pragma unroll
        for (int o = 16; o > 0; o >>= 1) {
            float ov = __shfl_down_sync(0xffffffffu, best, o);
            int   oj = __shfl_down_sync(0xffffffffu, bj,   o);
            if (ov > best || (ov == best && oj < bj)) { best = ov; bj = oj; }
        }
        bj = __shfl_sync(0xffffffffu, bj, 0);
        if (lane == 0) g_tk[gw * TK + t] = bj;
        if ((bj & 31) == lane) vals[bj >> 5] = -2.f;
    }
}

// ---------------- symmetric adjacency bitmap from top-k lists --------------
__global__ void edge_kernel() {
    int idx = blockIdx.x * blockDim.x + threadIdx.x;
    if (idx >= NT * TK) return;
    int i = idx / TK;
    int j = g_tk[idx];
    atomicOr(&g_bm[i * BMW + (j >> 5)], 1u << (j & 31));
    atomicOr(&g_bm[j * BMW + (i >> 5)], 1u << (i & 31));
}

// ---------------- degree (row sums over mask; w is bitwise symmetric) ------
__global__ void deg_kernel() {
    int gw   = (blockIdx.x * blockDim.x + threadIdx.x) >> 5;
    int lane = threadIdx.x & 31;
    if (gw >= NT) return;
    float s = 0.f;
    for (int wi = lane; wi < NW; wi += 32) {
        unsigned m = g_bm[gw * BMW + wi];
        while (m) {
            int b = __ffs(m) - 1; m &= m - 1;
            s += g_w[(size_t)gw * NT + wi * 32 + b];
        }
    }
#pragma unroll
    for (int o = 16; o > 0; o >>= 1) s += __shfl_down_sync(0xffffffffu, s, o);
    if (lane == 0) g_dsi[gw] = sqrtf(1.0f / (s + 2.2204460492503131e-16f));
}

// ---------------- sparse out[i,:] = dsi_i * sum_j w_ij*dsi_j * v[j,:] ------
__global__ void spout_kernel(float* __restrict__ out) {
    int i = blockIdx.x;
    __shared__ int   nbr[1120];
    __shared__ float coef[1120];
    __shared__ int   s_cnt;
    int tid = threadIdx.x;
    if (tid == 0) {
        int off = 0;
        for (int wi = 0; wi < NW; wi++) {
            unsigned m = g_bm[i * BMW + wi];
            while (m) {
                int b = __ffs(m) - 1; m &= m - 1;
                nbr[off++] = wi * 32 + b;
            }
        }
        s_cnt = off;
    }
    __syncthreads();
    int cnt = s_cnt;
    for (int t = tid; t < cnt; t += blockDim.x) {
        int j = nbr[t];
        coef[t] = g_w[(size_t)i * NT + j] * g_dsi[j];
    }
    __syncthreads();
    float di = g_dsi[i];
    for (int c = tid; c < DM; c += blockDim.x) {
        float acc = 0.f;
        for (int t = 0; t < cnt; t++)
            acc += coef[t] * g_v[(size_t)nbr[t] * DM + c];
        out[(size_t)i * DM + c] = di * acc;
    }
}

// ---------------- host launcher --------------------------------------------
extern "C" void kernel_launch(void* const* d_in, const int* in_sizes, int n_in,
                              void* d_out, int out_size) {
    const float* sup = (const float*)d_in[0];   // [100,640,10,10]
    const float* qry = (const float*)d_in[2];   // [1000,640,10,10]
    const float* Wq  = (const float*)d_in[4];   // [640,640]
    const float* Wv  = (const float*)d_in[5];   // [640,640]
    float* out = (float*)d_out;                 // [1100,640]

    float *px, *pq, *pqp0, *pqp1, *pvp0, *pvp1, *pgp0, *pgp1;
    void* pbm;
    cudaGetSymbolAddress((void**)&px,  g_x);
    cudaGetSymbolAddress((void**)&pq,  g_q);
    cudaGetSymbolAddress((void**)&pqp0, g_qp0);
    cudaGetSymbolAddress((void**)&pqp1, g_qp1);
    cudaGetSymbolAddress((void**)&pvp0, g_vp0);
    cudaGetSymbolAddress((void**)&pvp1, g_vp1);
    cudaGetSymbolAddress((void**)&pgp0, g_gp0);
    cudaGetSymbolAddress((void**)&pgp1, g_gp1);
    cudaGetSymbolAddress(&pbm, g_bm);

    // zero the padding rows of g_x (pad rows propagate as zeros through GEMMs)
    cudaMemsetAsync(px + (size_t)NT * DM, 0, (size_t)(NTP - NT) * DM * sizeof(float));

    // 1) spatial mean
    mean_kernel<<<(NT * DM * 32 + 255) / 256, 256>>>(sup, qry);

    // 2) emb_q / emb_v = x @ W^T, K-split=2 fused over both weights (z=4)
    {
        dim3 grid(DM / 64, NTP / 128, 4);
        gemm_ksplit<<<grid, 256>>>(px, Wq, Wv, pqp0, pvp0, pqp1, pvp1, DM, DM);
    }
    combine_qv_kernel<<<NTP, 160>>>();

    // 3) Gram = emb_q @ emb_q^T, K-split=2
    {
        dim3 grid(NTP / 64, NTP / 128, 2);
        gemm_ksplit<<<grid, 256>>>(pq, pq, pq, pgp0, pgp1, pgp0, pgp1, DM, NTP);
    }
    combine_gram_kernel<<<RB, 256>>>();
    reduce_final_kernel<<<1, RB>>>();

    // 4) fused exp transform + top-k
    int wr_blocks = (NT * 32 + 255) / 256;
    topk_kernel<<<wr_blocks, 256>>>();

    // 5) symmetric mask bitmap + degrees
    cudaMemsetAsync(pbm, 0, sizeof(unsigned) * NT * BMW);
    edge_kernel<<<(NT * TK + 255) / 256, 256>>>();
    deg_kernel<<<wr_blocks, 256>>>();

    // 6) sparse S @ emb_v with Laplacian scaling folded in
    spout_kernel<<<NT, 256>>>(out);
}

// round 16
// speedup vs baseline: 1.0885x; 1.0321x over previous
#include <cuda_runtime.h>
#include <math.h>

// Problem constants
#define NT   1100            // 100 support + 1000 query
#define NTP  1152            // NT padded to multiple of 128 (GEMM tiles)
#define DM   640             // d_model
#define NSUP 100
#define SP   100             // 10*10 spatial
#define TK   10              // top-k
#define RB   256             // reduction blocks (fixed for determinism)
#define BMW  40              // bitmap words per row (ceil(1100/32)=35, padded)
#define NW   35              // bitmap words actually used

// ---------------- scratch (device globals; no allocation allowed) ----------
__device__ float    g_x  [NTP * DM];             // spatial means (padded rows = 0)
__device__ float    g_q  [NTP * DM];             // emb_q
__device__ float    g_v  [NTP * DM];             // emb_v
__device__ float    g_qp0[NTP * DM];             // K-split partials
__device__ float    g_qp1[NTP * DM];
__device__ float    g_vp0[NTP * DM];
__device__ float    g_vp1[NTP * DM];
__device__ float    g_gp0[(size_t)NTP * NTP];    // gram K-split partials (4-way)
__device__ float    g_gp1[(size_t)NTP * NTP];
__device__ float    g_gp2[(size_t)NTP * NTP];
__device__ float    g_gp3[(size_t)NTP * NTP];
__device__ float    g_sq [NT];                   // ||emb_q_i||^2
__device__ float    g_w  [(size_t)NT * NT];      // distances, then exp-kernel
__device__ int      g_tk [NT * TK];              // topk indices per row
__device__ unsigned g_bm [NT * BMW];             // symmetric adjacency bitmap
__device__ float    g_dsi[NT];                   // D^{-1/2}
__device__ double   g_ps [RB];                   // partial sums
__device__ double   g_pq [RB];                   // partial sums of squares
__device__ float    g_invstd;

// packed f32x2 FMA (Blackwell; ptxas never emits FFMA2 from C++ — PTX only)
#define FMA2(acc, a, b) \
    asm("fma.rn.f32x2 %0, %1, %2, %0;" : "+l"(acc) : "l"(a), "l"(b))

// ---------------- 1) spatial mean: x[n,c] = mean_s emb[n,c,s] --------------
__global__ void mean_kernel(const float* __restrict__ sup,
                            const float* __restrict__ qry) {
    int gw   = (blockIdx.x * blockDim.x + threadIdx.x) >> 5;
    int lane = threadIdx.x & 31;
    if (gw >= NT * DM) return;
    int n = gw / DM, c = gw - n * DM;
    const float* p = (n < NSUP)
        ? (sup + (size_t)n * DM * SP + (size_t)c * SP)
        : (qry + (size_t)(n - NSUP) * DM * SP + (size_t)c * SP);
    float s = 0.f;
    if (lane < 25) {
        float4 v = ((const float4*)p)[lane];
        s = (v.x + v.y) + (v.z + v.w);
    }
#pragma unroll
    for (int o = 16; o > 0; o >>= 1) s += __shfl_down_sync(0xffffffffu, s, o);
    if (lane == 0) g_x[gw] = s * (1.0f / SP);
}

// ---------------- 128x128-tile fp32 GEMM, 8x8 micro, FFMA2 core ------------
// GRAM=0: C = A @ B^T, grid (5, 9, 4): z=(wsel|ksel<<1), K-split 2.
// GRAM=1: C = A @ A^T, ONLY lower-triangle tiles: grid (45, 1, 4), z = ksel
//         (K-split 4). Partial tiles stored unguarded to padded buffers.
// B tile stored pair-permuted: float col offset for source col n is
//   poff(n) = ((n>>1)&3)*32 + (n>>3)*2 + (n&1)
// so the inner loop reads 4 conflict-free ld.shared.b64, each an f32x2
// col-pair ready for FFMA2.
template<int GRAM>
__global__ void __launch_bounds__(256, 2)
gemm88(const float* __restrict__ A,
       const float* __restrict__ Bq, const float* __restrict__ Bv,
       float* __restrict__ C0, float* __restrict__ C1,
       float* __restrict__ C2, float* __restrict__ C3) {
    int row0, col0, koff, nk, ldc;
    const float* __restrict__ B;
    float* __restrict__ C;
    int z = blockIdx.z;
    if (GRAM) {
        int t = blockIdx.x;                 // lower-triangle tile id, 0..44
        int bi = 0;
        while ((bi + 1) * (bi + 2) / 2 <= t) bi++;
        int bj = t - bi * (bi + 1) / 2;
        row0 = bi * 128; col0 = bj * 128;
        ldc = NTP;
        koff = z * (DM / 4); nk = (DM / 4) / 8;    // 160-wide K quarters
        B = A;
        C = (z == 0) ? C0 : (z == 1) ? C1 : (z == 2) ? C2 : C3;
    } else {
        row0 = blockIdx.y * 128; col0 = blockIdx.x * 128;
        ldc = DM;
        int wsel = z & 1, ksel = z >> 1;
        koff = ksel * (DM / 2); nk = (DM / 2) / 8; // 320-wide K halves
        B = wsel ? Bv : Bq;
        C = (z == 0) ? C0 : (z == 1) ? C1 : (z == 2) ? C2 : C3;
    }

    __shared__ __align__(16) float As[2][8][132];
    __shared__ __align__(16) float Bs[2][8][132];

    int tid = threadIdx.x;            // 256 threads
    int tx = tid & 15, ty = tid >> 4; // micro 8x8: rows ty*8+, cols tx*8+
    int lrow = tid >> 1, lh = tid & 1;            // tile fill: 128 rows x 2 half-k

    const float4* Ap = (const float4*)(A + (size_t)(row0 + lrow) * DM + koff + lh * 4);
    const float4* Bp = (const float4*)(B + (size_t)(col0 + lrow) * DM + koff + lh * 4);

    // permuted float offset for B column lrow
    int po = ((lrow >> 1) & 3) * 32 + (lrow >> 3) * 2 + (lrow & 1);

    unsigned sA = (unsigned)__cvta_generic_to_shared(&As[0][0][0]);
    unsigned sB = (unsigned)__cvta_generic_to_shared(&Bs[0][0][0]);
    const unsigned TSZ = 8 * 132 * 4;

    unsigned long long acc[8][4];     // [row][col-pair], packed f32x2
#pragma unroll
    for (int r = 0; r < 8; r++)
#pragma unroll
        for (int m = 0; m < 4; m++) acc[r][m] = 0ull;

    float4 av = Ap[0];
    float4 bv = Bp[0];

    int buf = 0;
    As[buf][lh * 4 + 0][lrow] = av.x;
    As[buf][lh * 4 + 1][lrow] = av.y;
    As[buf][lh * 4 + 2][lrow] = av.z;
    As[buf][lh * 4 + 3][lrow] = av.w;
    Bs[buf][lh * 4 + 0][po] = bv.x;
    Bs[buf][lh * 4 + 1][po] = bv.y;
    Bs[buf][lh * 4 + 2][po] = bv.z;
    Bs[buf][lh * 4 + 3][po] = bv.w;
    __syncthreads();

#define GEMM88_INNER(bufA, bufB)                                                 \
    _Pragma("unroll")                                                            \
    for (int k = 0; k < 8; k++) {                                                \
        unsigned aaddr = (bufA) + k * 528 + ty * 32;                             \
        unsigned baddr = (bufB) + k * 528 + tx * 8;                              \
        float a0, a1, a2, a3, a4, a5, a6, a7;                                    \
        unsigned long long ad0, ad1, ad2, ad3, ad4, ad5, ad6, ad7;               \
        unsigned long long bp0, bp1, bp2, bp3;                                   \
        asm volatile("ld.shared.v4.f32 {%0,%1,%2,%3}, [%4];"                     \
            : "=f"(a0), "=f"(a1), "=f"(a2), "=f"(a3) : "r"(aaddr));              \
        asm volatile("ld.shared.v4.f32 {%0,%1,%2,%3}, [%4];"                     \
            : "=f"(a4), "=f"(a5), "=f"(a6), "=f"(a7) : "r"(aaddr + 16));         \
        asm volatile("ld.shared.b64 %0, [%1];" : "=l"(bp0) : "r"(baddr));        \
        asm volatile("ld.shared.b64 %0, [%1];" : "=l"(bp1) : "r"(baddr + 128));  \
        asm volatile("ld.shared.b64 %0, [%1];" : "=l"(bp2) : "r"(baddr + 256));  \
        asm volatile("ld.shared.b64 %0, [%1];" : "=l"(bp3) : "r"(baddr + 384));  \
        asm("mov.b64 %0, {%1,%1};" : "=l"(ad0) : "f"(a0));                       \
        asm("mov.b64 %0, {%1,%1};" : "=l"(ad1) : "f"(a1));                       \
        asm("mov.b64 %0, {%1,%1};" : "=l"(ad2) : "f"(a2));                       \
        asm("mov.b64 %0, {%1,%1};" : "=l"(ad3) : "f"(a3));                       \
        asm("mov.b64 %0, {%1,%1};" : "=l"(ad4) : "f"(a4));                       \
        asm("mov.b64 %0, {%1,%1};" : "=l"(ad5) : "f"(a5));                       \
        asm("mov.b64 %0, {%1,%1};" : "=l"(ad6) : "f"(a6));                       \
        asm("mov.b64 %0, {%1,%1};" : "=l"(ad7) : "f"(a7));                       \
        FMA2(acc[0][0], ad0, bp0); FMA2(acc[0][1], ad0, bp1);                    \
        FMA2(acc[0][2], ad0, bp2); FMA2(acc[0][3], ad0, bp3);                    \
        FMA2(acc[1][0], ad1, bp0); FMA2(acc[1][1], ad1, bp1);                    \
        FMA2(acc[1][2], ad1, bp2); FMA2(acc[1][3], ad1, bp3);                    \
        FMA2(acc[2][0], ad2, bp0); FMA2(acc[2][1], ad2, bp1);                    \
        FMA2(acc[2][2], ad2, bp2); FMA2(acc[2][3], ad2, bp3);                    \
        FMA2(acc[3][0], ad3, bp0); FMA2(acc[3][1], ad3, bp1);                    \
        FMA2(acc[3][2], ad3, bp2); FMA2(acc[3][3], ad3, bp3);                    \
        FMA2(acc[4][0], ad4, bp0); FMA2(acc[4][1], ad4, bp1);                    \
        FMA2(acc[4][2], ad4, bp2); FMA2(acc[4][3], ad4, bp3);                    \
        FMA2(acc[5][0], ad5, bp0); FMA2(acc[5][1], ad5, bp1);                    \
        FMA2(acc[5][2], ad5, bp2); FMA2(acc[5][3], ad5, bp3);                    \
        FMA2(acc[6][0], ad6, bp0); FMA2(acc[6][1], ad6, bp1);                    \
        FMA2(acc[6][2], ad6, bp2); FMA2(acc[6][3], ad6, bp3);                    \
        FMA2(acc[7][0], ad7, bp0); FMA2(acc[7][1], ad7, bp1);                    \
        FMA2(acc[7][2], ad7, bp2); FMA2(acc[7][3], ad7, bp3);                    \
    }

    for (int kt = 1; kt < nk; kt++) {
        av = Ap[kt * 2];
        bv = Bp[kt * 2];

        GEMM88_INNER(sA + buf * TSZ, sB + buf * TSZ);

        int nb = buf ^ 1;
        As[nb][lh * 4 + 0][lrow] = av.x;
        As[nb][lh * 4 + 1][lrow] = av.y;
        As[nb][lh * 4 + 2][lrow] = av.z;
        As[nb][lh * 4 + 3][lrow] = av.w;
        Bs[nb][lh * 4 + 0][po] = bv.x;
        Bs[nb][lh * 4 + 1][po] = bv.y;
        Bs[nb][lh * 4 + 2][po] = bv.z;
        Bs[nb][lh * 4 + 3][po] = bv.w;
        __syncthreads();
        buf = nb;
    }
    GEMM88_INNER(sA + buf * TSZ, sB + buf * TSZ);
#undef GEMM88_INNER

    // store: acc[r][m] holds cols (tx*8+2m, tx*8+2m+1) of row ty*8+r
#pragma unroll
    for (int r = 0; r < 8; r++) {
        float c0, c1, c2, c3, c4, c5, c6, c7;
        asm("mov.b64 {%0,%1}, %2;" : "=f"(c0), "=f"(c1) : "l"(acc[r][0]));
        asm("mov.b64 {%0,%1}, %2;" : "=f"(c2), "=f"(c3) : "l"(acc[r][1]));
        asm("mov.b64 {%0,%1}, %2;" : "=f"(c4), "=f"(c5) : "l"(acc[r][2]));
        asm("mov.b64 {%0,%1}, %2;" : "=f"(c6), "=f"(c7) : "l"(acc[r][3]));
        size_t base = (size_t)(row0 + ty * 8 + r) * ldc + col0 + tx * 8;
        *(float4*)(C + base)     = make_float4(c0, c1, c2, c3);
        *(float4*)(C + base + 4) = make_float4(c4, c5, c6, c7);
    }
}

// ---------------- combine qv partials + fused ||q||^2 ----------------------
__global__ void __launch_bounds__(160) combine_qv_kernel() {
    int r = blockIdx.x;                 // 0..NTP-1
    int t = threadIdx.x;                // 0..159
    size_t base = (size_t)r * DM;
    float4 q0 = ((const float4*)(g_qp0 + base))[t];
    float4 q1 = ((const float4*)(g_qp1 + base))[t];
    float4 q  = make_float4(q0.x + q1.x, q0.y + q1.y, q0.z + q1.z, q0.w + q1.w);
    ((float4*)(g_q + base))[t] = q;
    float4 v0 = ((const float4*)(g_vp0 + base))[t];
    float4 v1 = ((const float4*)(g_vp1 + base))[t];
    ((float4*)(g_v + base))[t] =
        make_float4(v0.x + v1.x, v0.y + v1.y, v0.z + v1.z, v0.w + v1.w);

    float s = q.x * q.x + q.y * q.y + q.z * q.z + q.w * q.w;
#pragma unroll
    for (int o = 16; o > 0; o >>= 1) s += __shfl_down_sync(0xffffffffu, s, o);
    __shared__ float ws[5];
    if ((t & 31) == 0) ws[t >> 5] = s;
    __syncthreads();
    if (t == 0 && r < NT)
        g_sq[r] = (ws[0] + ws[1]) + (ws[2] + ws[3]) + ws[4];
}

// ---------------- combine gram partials -> distances + fused sum/sumsq -----
// lower triangle only (j <= i); mirrors to (j,i); off-diag counted twice
__global__ void __launch_bounds__(256) combine_gram_kernel() {
    int tid = threadIdx.x;
    double s = 0.0, q = 0.0;
    for (int i = blockIdx.x; i < NT; i += gridDim.x) {
        float sqi = g_sq[i];
        const float* p0 = g_gp0 + (size_t)i * NTP;
        const float* p1 = g_gp1 + (size_t)i * NTP;
        const float* p2 = g_gp2 + (size_t)i * NTP;
        const float* p3 = g_gp3 + (size_t)i * NTP;
        float* wrow = g_w + (size_t)i * NT;
        for (int j = tid; j <= i; j += 256) {
            float p = (p0[j] + p1[j]) + (p2[j] + p3[j]);
            float d = (i == j) ? 0.f : fmaxf(sqi + g_sq[j] - 2.0f * p, 0.f);
            wrow[j] = d;
            g_w[(size_t)j * NT + i] = d;
            double dv = (double)d;
            s += 2.0 * dv; q += 2.0 * dv * dv;   // both (i,j) and (j,i); diag d=0
        }
    }
    __shared__ double ss[256], qq[256];
    ss[tid] = s; qq[tid] = q; __syncthreads();
    for (int st = 128; st > 0; st >>= 1) {
        if (tid < st) { ss[tid] += ss[tid + st]; qq[tid] += qq[tid + st]; }
        __syncthreads();
    }
    if (tid == 0) { g_ps[blockIdx.x] = ss[0]; g_pq[blockIdx.x] = qq[0]; }
}

__global__ void reduce_final_kernel() {
    __shared__ double ss[RB], qq[RB];
    ss[threadIdx.x] = g_ps[threadIdx.x];
    qq[threadIdx.x] = g_pq[threadIdx.x];
    __syncthreads();
    for (int st = RB / 2; st > 0; st >>= 1) {
        if (threadIdx.x < st) {
            ss[threadIdx.x] += ss[threadIdx.x + st];
            qq[threadIdx.x] += qq[threadIdx.x + st];
        }
        __syncthreads();
    }
    if (threadIdx.x == 0) {
        double cnt = (double)NT * NT - NT;
        double sum = ss[0], sumsq = qq[0];
        double var = (sumsq - sum * sum / cnt) / (cnt - 1.0);   // unbiased
        g_invstd = (float)(1.0 / sqrt(var));
    }
}

// ---------------- fused transform + per-row top-10 (warp per row) ----------
__global__ void topk_kernel() {
    int gw   = (blockIdx.x * blockDim.x + threadIdx.x) >> 5;
    int lane = threadIdx.x & 31;
    if (gw >= NT) return;
    float is = g_invstd;
    float* row = g_w + (size_t)gw * NT;
    float vals[NW];
#pragma unroll
    for (int s = 0; s < NW; s++) {
        int j = lane + 32 * s;
        float e = -2.f;
        if (j < NT) { e = __expf(-0.5f * row[j] * is); row[j] = e; }
        vals[s] = e;
    }
    for (int t = 0; t < TK; t++) {
        float best = -3.f; int bslot = 0;
#pragma unroll
        for (int s = 0; s < NW; s++) {
            if (vals[s] > best) { best = vals[s]; bslot = s; }
        }
        int bj = lane + 32 * bslot;
#pragma unroll
        for (int o = 16; o > 0; o >>= 1) {
            float ov = __shfl_down_sync(0xffffffffu, best, o);
            int   oj = __shfl_down_sync(0xffffffffu, bj,   o);
            if (ov > best || (ov == best && oj < bj)) { best = ov; bj = oj; }
        }
        bj = __shfl_sync(0xffffffffu, bj, 0);
        if (lane == 0) g_tk[gw * TK + t] = bj;
        if ((bj & 31) == lane) vals[bj >> 5] = -2.f;
    }
}

// ---------------- symmetric adjacency bitmap from top-k lists --------------
__global__ void edge_kernel() {
    int idx = blockIdx.x * blockDim.x + threadIdx.x;
    if (idx >= NT * TK) return;
    int i = idx / TK;
    int j = g_tk[idx];
    atomicOr(&g_bm[i * BMW + (j >> 5)], 1u << (j & 31));
    atomicOr(&g_bm[j * BMW + (i >> 5)], 1u << (i & 31));
}

// ---------------- degree (row sums over mask; w is bitwise symmetric) ------
__global__ void deg_kernel() {
    int gw   = (blockIdx.x * blockDim.x + threadIdx.x) >> 5;
    int lane = threadIdx.x & 31;
    if (gw >= NT) return;
    float s = 0.f;
    for (int wi = lane; wi < NW; wi += 32) {
        unsigned m = g_bm[gw * BMW + wi];
        while (m) {
            int b = __ffs(m) - 1; m &= m - 1;
            s += g_w[(size_t)gw * NT + wi * 32 + b];
        }
    }
#pragma unroll
    for (int o = 16; o > 0; o >>= 1) s += __shfl_down_sync(0xffffffffu, s, o);
    if (lane == 0) g_dsi[gw] = sqrtf(1.0f / (s + 2.2204460492503131e-16f));
}

// ---------------- sparse out[i,:] = dsi_i * sum_j w_ij*dsi_j * v[j,:] ------
__global__ void spout_kernel(float* __restrict__ out) {
    int i = blockIdx.x;
    __shared__ int   nbr[1120];
    __shared__ float coef[1120];
    __shared__ int   s_cnt;
    int tid = threadIdx.x;
    if (tid == 0) {
        int off = 0;
        for (int wi = 0; wi < NW; wi++) {
            unsigned m = g_bm[i * BMW + wi];
            while (m) {
                int b = __ffs(m) - 1; m &= m - 1;
                nbr[off++] = wi * 32 + b;
            }
        }
        s_cnt = off;
    }
    __syncthreads();
    int cnt = s_cnt;
    for (int t = tid; t < cnt; t += blockDim.x) {
        int j = nbr[t];
        coef[t] = g_w[(size_t)i * NT + j] * g_dsi[j];
    }
    __syncthreads();
    float di = g_dsi[i];
    for (int c = tid; c < DM; c += blockDim.x) {
        float acc = 0.f;
        for (int t = 0; t < cnt; t++)
            acc += coef[t] * g_v[(size_t)nbr[t] * DM + c];
        out[(size_t)i * DM + c] = di * acc;
    }
}

// ---------------- host launcher --------------------------------------------
extern "C" void kernel_launch(void* const* d_in, const int* in_sizes, int n_in,
                              void* d_out, int out_size) {
    const float* sup = (const float*)d_in[0];   // [100,640,10,10]
    const float* qry = (const float*)d_in[2];   // [1000,640,10,10]
    const float* Wq  = (const float*)d_in[4];   // [640,640]
    const float* Wv  = (const float*)d_in[5];   // [640,640]
    float* out = (float*)d_out;                 // [1100,640]

    float *px, *pq, *pqp0, *pqp1, *pvp0, *pvp1, *pgp0, *pgp1, *pgp2, *pgp3;
    void* pbm;
    cudaGetSymbolAddress((void**)&px,  g_x);
    cudaGetSymbolAddress((void**)&pq,  g_q);
    cudaGetSymbolAddress((void**)&pqp0, g_qp0);
    cudaGetSymbolAddress((void**)&pqp1, g_qp1);
    cudaGetSymbolAddress((void**)&pvp0, g_vp0);
    cudaGetSymbolAddress((void**)&pvp1, g_vp1);
    cudaGetSymbolAddress((void**)&pgp0, g_gp0);
    cudaGetSymbolAddress((void**)&pgp1, g_gp1);
    cudaGetSymbolAddress((void**)&pgp2, g_gp2);
    cudaGetSymbolAddress((void**)&pgp3, g_gp3);
    cudaGetSymbolAddress(&pbm, g_bm);

    // zero the padding rows of g_x (pad rows propagate as zeros through GEMMs)
    cudaMemsetAsync(px + (size_t)NT * DM, 0, (size_t)(NTP - NT) * DM * sizeof(float));

    // 1) spatial mean
    mean_kernel<<<(NT * DM * 32 + 255) / 256, 256>>>(sup, qry);

    // 2) emb_q / emb_v = x @ W^T, K-split=2 fused over both weights
    {
        dim3 grid(DM / 128, NTP / 128, 4);      // (5, 9, 4) = 180 blocks
        gemm88<0><<<grid, 256>>>(px, Wq, Wv, pqp0, pvp0, pqp1, pvp1);
    }
    combine_qv_kernel<<<NTP, 160>>>();

    // 3) Gram = emb_q @ emb_q^T, lower-triangle tiles only, K-split=4
    {
        dim3 grid(45, 1, 4);                    // 180 blocks
        gemm88<1><<<grid, 256>>>(pq, pq, pq, pgp0, pgp1, pgp2, pgp3);
    }
    combine_gram_kernel<<<RB, 256>>>();
    reduce_final_kernel<<<1, RB>>>();

    // 4) fused exp transform + top-k
    int wr_blocks = (NT * 32 + 255) / 256;
    topk_kernel<<<wr_blocks, 256>>>();

    // 5) symmetric mask bitmap + degrees
    cudaMemsetAsync(pbm, 0, sizeof(unsigned) * NT * BMW);
    edge_kernel<<<(NT * TK + 255) / 256, 256>>>();
    deg_kernel<<<wr_blocks, 256>>>();

    // 6) sparse S @ emb_v with Laplacian scaling folded in
    spout_kernel<<<NT, 256>>>(out);
}

// round 17
// speedup vs baseline: 1.1361x; 1.0437x over previous
#include <cuda_runtime.h>
#include <math.h>

// Problem constants
#define NT   1100            // 100 support + 1000 query
#define NTP  1152            // NT padded to multiple of 128 (GEMM tiles)
#define DM   640             // d_model
#define NSUP 100
#define SP   100             // 10*10 spatial
#define TK   10              // top-k
#define CGT  630             // combine tiles: 35*36/2 lower-tri 32x32 tiles
#define BMW  40              // bitmap words per row (ceil(1100/32)=35, padded)
#define NW   35              // bitmap words actually used

// ---------------- scratch (device globals; no allocation allowed) ----------
__device__ float    g_x  [NTP * DM];             // spatial means (padded rows = 0)
__device__ float    g_q  [NTP * DM];             // emb_q
__device__ float    g_v  [NTP * DM];             // emb_v
__device__ float    g_qp [4][NTP * DM];          // q K-split partials
__device__ float    g_vp [4][NTP * DM];          // v K-split partials
__device__ float    g_gp [8][(size_t)NTP * NTP]; // gram K-split partials
__device__ float    g_sq [NT];                   // ||emb_q_i||^2
__device__ float    g_w  [(size_t)NT * NT];      // distances, then exp-kernel
__device__ int      g_tk [NT * TK];              // topk indices per row
__device__ unsigned g_bm [NT * BMW];             // symmetric adjacency bitmap
__device__ float    g_dsi[NT];                   // D^{-1/2}
__device__ double   g_ps [CGT];                  // partial sums
__device__ double   g_pq [CGT];                  // partial sums of squares
__device__ float    g_invstd;

// packed f32x2 FMA (Blackwell; ptxas never emits FFMA2 from C++ — PTX only)
#define FMA2(acc, a, b) \
    asm("fma.rn.f32x2 %0, %1, %2, %0;" : "+l"(acc) : "l"(a), "l"(b))

// ---------------- 1) spatial mean: x[n,c] = mean_s emb[n,c,s] --------------
__global__ void mean_kernel(const float* __restrict__ sup,
                            const float* __restrict__ qry) {
    int gw   = (blockIdx.x * blockDim.x + threadIdx.x) >> 5;
    int lane = threadIdx.x & 31;
    if (gw >= NT * DM) return;
    int n = gw / DM, c = gw - n * DM;
    const float* p = (n < NSUP)
        ? (sup + (size_t)n * DM * SP + (size_t)c * SP)
        : (qry + (size_t)(n - NSUP) * DM * SP + (size_t)c * SP);
    float s = 0.f;
    if (lane < 25) {
        float4 v = ((const float4*)p)[lane];
        s = (v.x + v.y) + (v.z + v.w);
    }
#pragma unroll
    for (int o = 16; o > 0; o >>= 1) s += __shfl_down_sync(0xffffffffu, s, o);
    if (lane == 0) g_x[gw] = s * (1.0f / SP);
}

// ---------------- 128x128-tile fp32 GEMM, 8x8 micro, FFMA2, BK=16 ----------
// GRAM=0: C = A @ B^T, grid (5, 9, 8): wsel=z&1, ksel=z>>1 (K-split 4).
// GRAM=1: C = A @ A^T, lower-triangle tiles: grid (45, 1, 8), ksel=z (K/8).
// Partial tiles stored unguarded to padded buffers (ldc = DM or NTP).
// B tile pair-permuted: poff(n) = ((n>>1)&3)*32 + (n>>3)*2 + (n&1) so the
// inner loop reads conflict-free ld.shared.b64 f32x2 col-pairs.
template<int GRAM>
__global__ void __launch_bounds__(256, 2)
gemm88(const float* __restrict__ A,
       const float* __restrict__ Bq, const float* __restrict__ Bv,
       float* __restrict__ C0, float* __restrict__ C1,
       float* __restrict__ C2, float* __restrict__ C3,
       float* __restrict__ C4, float* __restrict__ C5,
       float* __restrict__ C6, float* __restrict__ C7) {
    int row0, col0, koff, nk, ldc;
    const float* __restrict__ B;
    float* __restrict__ C;
    int z = blockIdx.z;
    switch (z) {
        case 0: C = C0; break; case 1: C = C1; break;
        case 2: C = C2; break; case 3: C = C3; break;
        case 4: C = C4; break; case 5: C = C5; break;
        case 6: C = C6; break; default: C = C7; break;
    }
    if (GRAM) {
        int t = blockIdx.x;                 // lower-triangle tile id, 0..44
        int bi = 0;
        while ((bi + 1) * (bi + 2) / 2 <= t) bi++;
        int bj = t - bi * (bi + 1) / 2;
        row0 = bi * 128; col0 = bj * 128;
        ldc = NTP;
        koff = z * (DM / 8); nk = (DM / 8) / 16;   // 80-wide K eighths, nk=5
        B = A;
    } else {
        row0 = blockIdx.y * 128; col0 = blockIdx.x * 128;
        ldc = DM;
        int wsel = z & 1, ksel = z >> 1;
        koff = ksel * (DM / 4); nk = (DM / 4) / 16; // 160-wide quarters, nk=10
        B = wsel ? Bv : Bq;
    }

    __shared__ __align__(16) float As[2][16][132];
    __shared__ __align__(16) float Bs[2][16][132];

    int tid = threadIdx.x;            // 256 threads
    int tx = tid & 15, ty = tid >> 4; // micro 8x8: rows ty*8+, cols tx*8+
    int lrow = tid >> 1, lh = tid & 1;            // tile fill: 128 rows x 2 groups

    const float4* Ap = (const float4*)(A + (size_t)(row0 + lrow) * DM + koff + lh * 4);
    const float4* Bp = (const float4*)(B + (size_t)(col0 + lrow) * DM + koff + lh * 4);

    // permuted float offset for B column lrow
    int po = ((lrow >> 1) & 3) * 32 + (lrow >> 3) * 2 + (lrow & 1);

    unsigned sA = (unsigned)__cvta_generic_to_shared(&As[0][0][0]);
    unsigned sB = (unsigned)__cvta_generic_to_shared(&Bs[0][0][0]);
    const unsigned TSZ = 16 * 132 * 4;

    unsigned long long acc[8][4];     // [row][col-pair], packed f32x2
#pragma unroll
    for (int r = 0; r < 8; r++)
#pragma unroll
        for (int m = 0; m < 4; m++) acc[r][m] = 0ull;

    // k-groups covered by this thread: lh*4..lh*4+3 and lh*4+8..lh*4+11
    float4 av0 = Ap[0], av1 = Ap[2];
    float4 bv0 = Bp[0], bv1 = Bp[2];

    int buf = 0;
    As[buf][lh * 4 + 0][lrow] = av0.x;
    As[buf][lh * 4 + 1][lrow] = av0.y;
    As[buf][lh * 4 + 2][lrow] = av0.z;
    As[buf][lh * 4 + 3][lrow] = av0.w;
    As[buf][lh * 4 + 8][lrow] = av1.x;
    As[buf][lh * 4 + 9][lrow] = av1.y;
    As[buf][lh * 4 + 10][lrow] = av1.z;
    As[buf][lh * 4 + 11][lrow] = av1.w;
    Bs[buf][lh * 4 + 0][po] = bv0.x;
    Bs[buf][lh * 4 + 1][po] = bv0.y;
    Bs[buf][lh * 4 + 2][po] = bv0.z;
    Bs[buf][lh * 4 + 3][po] = bv0.w;
    Bs[buf][lh * 4 + 8][po] = bv1.x;
    Bs[buf][lh * 4 + 9][po] = bv1.y;
    Bs[buf][lh * 4 + 10][po] = bv1.z;
    Bs[buf][lh * 4 + 11][po] = bv1.w;
    __syncthreads();

#define GEMM88_INNER(bufA, bufB)                                                 \
    _Pragma("unroll")                                                            \
    for (int k = 0; k < 16; k++) {                                               \
        unsigned aaddr = (bufA) + k * 528 + ty * 32;                             \
        unsigned baddr = (bufB) + k * 528 + tx * 8;                              \
        float a0, a1, a2, a3, a4, a5, a6, a7;                                    \
        unsigned long long ad0, ad1, ad2, ad3, ad4, ad5, ad6, ad7;               \
        unsigned long long bp0, bp1, bp2, bp3;                                   \
        asm volatile("ld.shared.v4.f32 {%0,%1,%2,%3}, [%4];"                     \
            : "=f"(a0), "=f"(a1), "=f"(a2), "=f"(a3) : "r"(aaddr));              \
        asm volatile("ld.shared.v4.f32 {%0,%1,%2,%3}, [%4];"                     \
            : "=f"(a4), "=f"(a5), "=f"(a6), "=f"(a7) : "r"(aaddr + 16));         \
        asm volatile("ld.shared.b64 %0, [%1];" : "=l"(bp0) : "r"(baddr));        \
        asm volatile("ld.shared.b64 %0, [%1];" : "=l"(bp1) : "r"(baddr + 128));  \
        asm volatile("ld.shared.b64 %0, [%1];" : "=l"(bp2) : "r"(baddr + 256));  \
        asm volatile("ld.shared.b64 %0, [%1];" : "=l"(bp3) : "r"(baddr + 384));  \
        asm("mov.b64 %0, {%1,%1};" : "=l"(ad0) : "f"(a0));                       \
        asm("mov.b64 %0, {%1,%1};" : "=l"(ad1) : "f"(a1));                       \
        asm("mov.b64 %0, {%1,%1};" : "=l"(ad2) : "f"(a2));                       \
        asm("mov.b64 %0, {%1,%1};" : "=l"(ad3) : "f"(a3));                       \
        asm("mov.b64 %0, {%1,%1};" : "=l"(ad4) : "f"(a4));                       \
        asm("mov.b64 %0, {%1,%1};" : "=l"(ad5) : "f"(a5));                       \
        asm("mov.b64 %0, {%1,%1};" : "=l"(ad6) : "f"(a6));                       \
        asm("mov.b64 %0, {%1,%1};" : "=l"(ad7) : "f"(a7));                       \
        FMA2(acc[0][0], ad0, bp0); FMA2(acc[0][1], ad0, bp1);                    \
        FMA2(acc[0][2], ad0, bp2); FMA2(acc[0][3], ad0, bp3);                    \
        FMA2(acc[1][0], ad1, bp0); FMA2(acc[1][1], ad1, bp1);                    \
        FMA2(acc[1][2], ad1, bp2); FMA2(acc[1][3], ad1, bp3);                    \
        FMA2(acc[2][0], ad2, bp0); FMA2(acc[2][1], ad2, bp1);                    \
        FMA2(acc[2][2], ad2, bp2); FMA2(acc[2][3], ad2, bp3);                    \
        FMA2(acc[3][0], ad3, bp0); FMA2(acc[3][1], ad3, bp1);                    \
        FMA2(acc[3][2], ad3, bp2); FMA2(acc[3][3], ad3, bp3);                    \
        FMA2(acc[4][0], ad4, bp0); FMA2(acc[4][1], ad4, bp1);                    \
        FMA2(acc[4][2], ad4, bp2); FMA2(acc[4][3], ad4, bp3);                    \
        FMA2(acc[5][0], ad5, bp0); FMA2(acc[5][1], ad5, bp1);                    \
        FMA2(acc[5][2], ad5, bp2); FMA2(acc[5][3], ad5, bp3);                    \
        FMA2(acc[6][0], ad6, bp0); FMA2(acc[6][1], ad6, bp1);                    \
        FMA2(acc[6][2], ad6, bp2); FMA2(acc[6][3], ad6, bp3);                    \
        FMA2(acc[7][0], ad7, bp0); FMA2(acc[7][1], ad7, bp1);                    \
        FMA2(acc[7][2], ad7, bp2); FMA2(acc[7][3], ad7, bp3);                    \
    }

    for (int kt = 1; kt < nk; kt++) {
        av0 = Ap[kt * 4]; av1 = Ap[kt * 4 + 2];
        bv0 = Bp[kt * 4]; bv1 = Bp[kt * 4 + 2];

        GEMM88_INNER(sA + buf * TSZ, sB + buf * TSZ);

        int nb = buf ^ 1;
        As[nb][lh * 4 + 0][lrow] = av0.x;
        As[nb][lh * 4 + 1][lrow] = av0.y;
        As[nb][lh * 4 + 2][lrow] = av0.z;
        As[nb][lh * 4 + 3][lrow] = av0.w;
        As[nb][lh * 4 + 8][lrow] = av1.x;
        As[nb][lh * 4 + 9][lrow] = av1.y;
        As[nb][lh * 4 + 10][lrow] = av1.z;
        As[nb][lh * 4 + 11][lrow] = av1.w;
        Bs[nb][lh * 4 + 0][po] = bv0.x;
        Bs[nb][lh * 4 + 1][po] = bv0.y;
        Bs[nb][lh * 4 + 2][po] = bv0.z;
        Bs[nb][lh * 4 + 3][po] = bv0.w;
        Bs[nb][lh * 4 + 8][po] = bv1.x;
        Bs[nb][lh * 4 + 9][po] = bv1.y;
        Bs[nb][lh * 4 + 10][po] = bv1.z;
        Bs[nb][lh * 4 + 11][po] = bv1.w;
        __syncthreads();
        buf = nb;
    }
    GEMM88_INNER(sA + buf * TSZ, sB + buf * TSZ);
#undef GEMM88_INNER

    // store: acc[r][m] holds cols (tx*8+2m, tx*8+2m+1) of row ty*8+r
#pragma unroll
    for (int r = 0; r < 8; r++) {
        float c0, c1, c2, c3, c4, c5, c6, c7;
        asm("mov.b64 {%0,%1}, %2;" : "=f"(c0), "=f"(c1) : "l"(acc[r][0]));
        asm("mov.b64 {%0,%1}, %2;" : "=f"(c2), "=f"(c3) : "l"(acc[r][1]));
        asm("mov.b64 {%0,%1}, %2;" : "=f"(c4), "=f"(c5) : "l"(acc[r][2]));
        asm("mov.b64 {%0,%1}, %2;" : "=f"(c6), "=f"(c7) : "l"(acc[r][3]));
        size_t base = (size_t)(row0 + ty * 8 + r) * ldc + col0 + tx * 8;
        *(float4*)(C + base)     = make_float4(c0, c1, c2, c3);
        *(float4*)(C + base + 4) = make_float4(c4, c5, c6, c7);
    }
}

// ---------------- combine qv partials (4-way) + fused ||q||^2 --------------
__global__ void __launch_bounds__(160) combine_qv_kernel() {
    int r = blockIdx.x;                 // 0..NTP-1
    int t = threadIdx.x;                // 0..159
    size_t base = (size_t)r * DM;
    float4 a = ((const float4*)(g_qp[0] + base))[t];
    float4 b = ((const float4*)(g_qp[1] + base))[t];
    float4 c = ((const float4*)(g_qp[2] + base))[t];
    float4 d = ((const float4*)(g_qp[3] + base))[t];
    float4 q = make_float4((a.x + b.x) + (c.x + d.x), (a.y + b.y) + (c.y + d.y),
                           (a.z + b.z) + (c.z + d.z), (a.w + b.w) + (c.w + d.w));
    ((float4*)(g_q + base))[t] = q;
    a = ((const float4*)(g_vp[0] + base))[t];
    b = ((const float4*)(g_vp[1] + base))[t];
    c = ((const float4*)(g_vp[2] + base))[t];
    d = ((const float4*)(g_vp[3] + base))[t];
    ((float4*)(g_v + base))[t] =
        make_float4((a.x + b.x) + (c.x + d.x), (a.y + b.y) + (c.y + d.y),
                    (a.z + b.z) + (c.z + d.z), (a.w + b.w) + (c.w + d.w));

    float s = q.x * q.x + q.y * q.y + q.z * q.z + q.w * q.w;
#pragma unroll
    for (int o = 16; o > 0; o >>= 1) s += __shfl_down_sync(0xffffffffu, s, o);
    __shared__ float ws[5];
    if ((t & 31) == 0) ws[t >> 5] = s;
    __syncthreads();
    if (t == 0 && r < NT)
        g_sq[r] = (ws[0] + ws[1]) + (ws[2] + ws[3]) + ws[4];
}

// ---------------- combine gram (8 partials) -> distances, tiled mirror -----
// one block per lower-tri 32x32 tile; smem transpose for coalesced mirror;
// fused sum/sumsq partials (off-diag counted twice; diag d = 0).
__global__ void __launch_bounds__(256) combine_gram_kernel() {
    int t = blockIdx.x;                 // 0..CGT-1, ti >= tj
    int ti = 0;
    while ((ti + 1) * (ti + 2) / 2 <= t) ti++;
    int tj = t - ti * (ti + 1) / 2;
    int i0 = ti * 32, j0 = tj * 32;

    __shared__ float tile[32][33];
    int tid = threadIdx.x;
    int r  = tid >> 3;                  // 0..31
    int c4 = tid & 7;                   // 0..7 (float4 col group)
    int i  = i0 + r;
    int jb = j0 + c4 * 4;

    double s = 0.0, q = 0.0;
    {
        float4 d4 = make_float4(0.f, 0.f, 0.f, 0.f);
        if (i < NT) {
            size_t off = (size_t)i * NTP + jb;
            float4 p = *(const float4*)(g_gp[0] + off);
            float4 p1 = *(const float4*)(g_gp[1] + off);
            float4 p2 = *(const float4*)(g_gp[2] + off);
            float4 p3 = *(const float4*)(g_gp[3] + off);
            float4 p4 = *(const float4*)(g_gp[4] + off);
            float4 p5 = *(const float4*)(g_gp[5] + off);
            float4 p6 = *(const float4*)(g_gp[6] + off);
            float4 p7 = *(const float4*)(g_gp[7] + off);
            float4 ps = make_float4(
                ((p.x + p1.x) + (p2.x + p3.x)) + ((p4.x + p5.x) + (p6.x + p7.x)),
                ((p.y + p1.y) + (p2.y + p3.y)) + ((p4.y + p5.y) + (p6.y + p7.y)),
                ((p.z + p1.z) + (p2.z + p3.z)) + ((p4.z + p5.z) + (p6.z + p7.z)),
                ((p.w + p1.w) + (p2.w + p3.w)) + ((p4.w + p5.w) + (p6.w + p7.w)));
            float sqi = g_sq[i];
            float pv[4] = {ps.x, ps.y, ps.z, ps.w};
            float dv[4];
#pragma unroll
            for (int k = 0; k < 4; k++) {
                int j = jb + k;
                float d = 0.f;
                if (j <= i) {           // j <= i < NT
                    d = (j == i) ? 0.f : fmaxf(sqi + g_sq[j] - 2.0f * pv[k], 0.f);
                    double dd = (double)d;
                    s += 2.0 * dd; q += 2.0 * dd * dd;
                }
                dv[k] = d;
            }
            d4 = make_float4(dv[0], dv[1], dv[2], dv[3]);
            // direct write (lower triangle only)
            if (jb + 3 <= i) {
                *(float4*)(g_w + (size_t)i * NT + jb) = d4;
            } else {
#pragma unroll
                for (int k = 0; k < 4; k++)
                    if (jb + k <= i) g_w[(size_t)i * NT + jb + k] = (&d4.x)[k];
            }
        }
        tile[r][c4 * 4 + 0] = d4.x;
        tile[r][c4 * 4 + 1] = d4.y;
        tile[r][c4 * 4 + 2] = d4.z;
        tile[r][c4 * 4 + 3] = d4.w;
    }
    __syncthreads();

    // mirror: write w[jj][ii] = tile[ii-i0][jj-j0] for strict-upper targets
    {
        int rr = r;                     // row of transposed tile = jj - j0
        int jj = j0 + rr;
#pragma unroll
        for (int k = 0; k < 4; k++) {
            int cc2 = c4 * 4 + k;       // col of transposed tile = ii - i0
            int ii = i0 + cc2;
            if (jj < ii && ii < NT)
                g_w[(size_t)jj * NT + ii] = tile[cc2][rr];
        }
    }

    // block partials (deterministic shapes)
    __shared__ double ss[256], qq[256];
    ss[tid] = s; qq[tid] = q; __syncthreads();
    for (int st = 128; st > 0; st >>= 1) {
        if (tid < st) { ss[tid] += ss[tid + st]; qq[tid] += qq[tid + st]; }
        __syncthreads();
    }
    if (tid == 0) { g_ps[blockIdx.x] = ss[0]; g_pq[blockIdx.x] = qq[0]; }
}

__global__ void reduce_final_kernel() {
    __shared__ double ss[256], qq[256];
    double s = 0.0, q = 0.0;
    for (int t = threadIdx.x; t < CGT; t += 256) { s += g_ps[t]; q += g_pq[t]; }
    ss[threadIdx.x] = s; qq[threadIdx.x] = q; __syncthreads();
    for (int st = 128; st > 0; st >>= 1) {
        if (threadIdx.x < st) {
            ss[threadIdx.x] += ss[threadIdx.x + st];
            qq[threadIdx.x] += qq[threadIdx.x + st];
        }
        __syncthreads();
    }
    if (threadIdx.x == 0) {
        double cnt = (double)NT * NT - NT;
        double sum = ss[0], sumsq = qq[0];
        double var = (sumsq - sum * sum / cnt) / (cnt - 1.0);   // unbiased
        g_invstd = (float)(1.0 / sqrt(var));
    }
}

// ---------------- fused transform + per-row top-10 (warp per row) ----------
__global__ void topk_kernel() {
    int gw   = (blockIdx.x * blockDim.x + threadIdx.x) >> 5;
    int lane = threadIdx.x & 31;
    if (gw >= NT) return;
    float is = g_invstd;
    float* row = g_w + (size_t)gw * NT;
    float vals[NW];
#pragma unroll
    for (int s = 0; s < NW; s++) {
        int j = lane + 32 * s;
        float e = -2.f;
        if (j < NT) { e = __expf(-0.5f * row[j] * is); row[j] = e; }
        vals[s] = e;
    }
    for (int t = 0; t < TK; t++) {
        float best = -3.f; int bslot = 0;
#pragma unroll
        for (int s = 0; s < NW; s++) {
            if (vals[s] > best) { best = vals[s]; bslot = s; }
        }
        int bj = lane + 32 * bslot;
#pragma unroll
        for (int o = 16; o > 0; o >>= 1) {
            float ov = __shfl_down_sync(0xffffffffu, best, o);
            int   oj = __shfl_down_sync(0xffffffffu, bj,   o);
            if (ov > best || (ov == best && oj < bj)) { best = ov; bj = oj; }
        }
        bj = __shfl_sync(0xffffffffu, bj, 0);
        if (lane == 0) g_tk[gw * TK + t] = bj;
        if ((bj & 31) == lane) vals[bj >> 5] = -2.f;
    }
}

// ---------------- symmetric adjacency bitmap from top-k lists --------------
__global__ void edge_kernel() {
    int idx = blockIdx.x * blockDim.x + threadIdx.x;
    if (idx >= NT * TK) return;
    int i = idx / TK;
    int j = g_tk[idx];
    atomicOr(&g_bm[i * BMW + (j >> 5)], 1u << (j & 31));
    atomicOr(&g_bm[j * BMW + (i >> 5)], 1u << (i & 31));
}

// ---------------- degree (row sums over mask; w is bitwise symmetric) ------
__global__ void deg_kernel() {
    int gw   = (blockIdx.x * blockDim.x + threadIdx.x) >> 5;
    int lane = threadIdx.x & 31;
    if (gw >= NT) return;
    float s = 0.f;
    for (int wi = lane; wi < NW; wi += 32) {
        unsigned m = g_bm[gw * BMW + wi];
        while (m) {
            int b = __ffs(m) - 1; m &= m - 1;
            s += g_w[(size_t)gw * NT + wi * 32 + b];
        }
    }
#pragma unroll
    for (int o = 16; o > 0; o >>= 1) s += __shfl_down_sync(0xffffffffu, s, o);
    if (lane == 0) g_dsi[gw] = sqrtf(1.0f / (s + 2.2204460492503131e-16f));
}

// ---------------- sparse out[i,:] = dsi_i * sum_j w_ij*dsi_j * v[j,:] ------
__global__ void spout_kernel(float* __restrict__ out) {
    int i = blockIdx.x;
    __shared__ int   nbr[1120];
    __shared__ float coef[1120];
    __shared__ int   s_cnt;
    int tid = threadIdx.x;
    if (tid == 0) {
        int off = 0;
        for (int wi = 0; wi < NW; wi++) {
            unsigned m = g_bm[i * BMW + wi];
            while (m) {
                int b = __ffs(m) - 1; m &= m - 1;
                nbr[off++] = wi * 32 + b;
            }
        }
        s_cnt = off;
    }
    __syncthreads();
    int cnt = s_cnt;
    for (int t = tid; t < cnt; t += blockDim.x) {
        int j = nbr[t];
        coef[t] = g_w[(size_t)i * NT + j] * g_dsi[j];
    }
    __syncthreads();
    float di = g_dsi[i];
    for (int c = tid; c < DM; c += blockDim.x) {
        float acc = 0.f;
        for (int t = 0; t < cnt; t++)
            acc += coef[t] * g_v[(size_t)nbr[t] * DM + c];
        out[(size_t)i * DM + c] = di * acc;
    }
}

// ---------------- host launcher --------------------------------------------
extern "C" void kernel_launch(void* const* d_in, const int* in_sizes, int n_in,
                              void* d_out, int out_size) {
    const float* sup = (const float*)d_in[0];   // [100,640,10,10]
    const float* qry = (const float*)d_in[2];   // [1000,640,10,10]
    const float* Wq  = (const float*)d_in[4];   // [640,640]
    const float* Wv  = (const float*)d_in[5];   // [640,640]
    float* out = (float*)d_out;                 // [1100,640]

    float *px, *pq;
    float *pqp[4], *pvp[4], *pgp[8];
    void* pbm;
    cudaGetSymbolAddress((void**)&px, g_x);
    cudaGetSymbolAddress((void**)&pq, g_q);
    {
        float* base;
        cudaGetSymbolAddress((void**)&base, g_qp);
        for (int k = 0; k < 4; k++) pqp[k] = base + (size_t)k * NTP * DM;
        cudaGetSymbolAddress((void**)&base, g_vp);
        for (int k = 0; k < 4; k++) pvp[k] = base + (size_t)k * NTP * DM;
        cudaGetSymbolAddress((void**)&base, g_gp);
        for (int k = 0; k < 8; k++) pgp[k] = base + (size_t)k * NTP * NTP;
    }
    cudaGetSymbolAddress(&pbm, g_bm);

    // zero the padding rows of g_x (pad rows propagate as zeros through GEMMs)
    cudaMemsetAsync(px + (size_t)NT * DM, 0, (size_t)(NTP - NT) * DM * sizeof(float));

    // 1) spatial mean
    mean_kernel<<<(NT * DM * 32 + 255) / 256, 256>>>(sup, qry);

    // 2) emb_q / emb_v = x @ W^T, K-split=4 fused over both weights
    {
        dim3 grid(DM / 128, NTP / 128, 8);      // (5, 9, 8) = 360 blocks
        gemm88<0><<<grid, 256>>>(px, Wq, Wv,
                                 pqp[0], pvp[0], pqp[1], pvp[1],
                                 pqp[2], pvp[2], pqp[3], pvp[3]);
    }
    combine_qv_kernel<<<NTP, 160>>>();

    // 3) Gram = emb_q @ emb_q^T, lower-triangle tiles only, K-split=8
    {
        dim3 grid(45, 1, 8);                    // 360 blocks
        gemm88<1><<<grid, 256>>>(pq, pq, pq,
                                 pgp[0], pgp[1], pgp[2], pgp[3],
                                 pgp[4], pgp[5], pgp[6], pgp[7]);
    }
    combine_gram_kernel<<<CGT, 256>>>();
    reduce_final_kernel<<<1, 256>>>();

    // 4) fused exp transform + top-k
    int wr_blocks = (NT * 32 + 255) / 256;
    topk_kernel<<<wr_blocks, 256>>>();

    // 5) symmetric mask bitmap + degrees
    cudaMemsetAsync(pbm, 0, sizeof(unsigned) * NT * BMW);
    edge_kernel<<<(NT * TK + 255) / 256, 256>>>();
    deg_kernel<<<wr_blocks, 256>>>();

    // 6) sparse S @ emb_v with Laplacian scaling folded in
    spout_kernel<<<NT, 256>>>(out);
}